// round 1
// baseline (speedup 1.0000x reference)
#include <cuda_runtime.h>
#include <cuda_bf16.h>

// Hawkes point-process log-likelihood, N=16, T=2048.
// Exact O(T) reformulation of the O(T^2) reference via the Hawkes recurrence:
//   A[i] = sum_{j<i} exp(-beta*(t_i - t_j)) = g[i]*(A[i-1]+1),
//   g[i] = exp(-beta*(t_i - t_{i-1})), A[0] = 0.
// Parallelized with a block-level affine scan (x -> P*x + Q per chunk);
// chunk P telescopes to a single exp.

#define TT 2048
#define BLK 256
#define CHUNK (TT / BLK)   // 8

__global__ __launch_bounds__(BLK)
void hawkes_kernel(const float* __restrict__ et,
                   const float* __restrict__ mask,
                   const float* __restrict__ t0p,
                   const float* __restrict__ t1p,
                   const float* __restrict__ mup,
                   const float* __restrict__ alphap,
                   const float* __restrict__ betap,
                   float* __restrict__ out)
{
    const int n = blockIdx.x;
    const int k = threadIdx.x;

    // softplus of the scalar params (redundant per thread, trivially cheap)
    const float mu    = log1pf(expf(mup[0]));
    const float alpha = log1pf(expf(alphap[0]));
    const float beta  = log1pf(expf(betap[0]));

    const float* t = et   + n * TT;
    const float* m = mask + n * TT;
    const float t0 = t0p[n];
    const float t1 = t1p[n];

    const int base = k * CHUNK;

    // ---- local pass: per-element g, local affine (P, Q) ----
    float tv[CHUNK], mv[CHUNK], g[CHUNK];
    float tm1 = (base == 0) ? 0.0f : t[base - 1];
    float tprev = tm1;
    float A = 0.0f;  // local Q (A value assuming A_in = 0)
    #pragma unroll
    for (int j = 0; j < CHUNK; ++j) {
        float tj = t[base + j];
        tv[j] = tj;
        mv[j] = m[base + j];
        float gj = (base + j == 0) ? 0.0f : expf(-beta * (tj - tprev));
        g[j] = gj;
        tprev = tj;
        A = gj * (A + 1.0f);
    }
    // chunk P: product of g over chunk telescopes to one exp.
    // k==0 contains global index 0 where g=0, so P_0 = 0.
    float P = (k == 0) ? 0.0f : expf(-beta * (tv[CHUNK - 1] - tm1));
    float Q = A;

    // ---- inclusive affine scan over 256 threads (Hillis-Steele) ----
    __shared__ float sP[BLK], sQ[BLK], sR[BLK];
    sP[k] = P; sQ[k] = Q;
    __syncthreads();
    #pragma unroll
    for (int d = 1; d < BLK; d <<= 1) {
        float p = sP[k], q = sQ[k];
        float np = p, nq = q;
        if (k >= d) {
            float pe = sP[k - d], qe = sQ[k - d];  // earlier segment
            np = p * pe;
            nq = p * qe + q;
        }
        __syncthreads();
        sP[k] = np; sQ[k] = nq;
        __syncthreads();
    }
    // A entering this thread's chunk = exclusive prefix applied to 0
    float Ain = (k == 0) ? 0.0f : sQ[k - 1];
    __syncthreads();

    // ---- replay: log-likelihood + compensator terms ----
    const float NEG = -1e20f;
    float A2 = Ain;
    float acc = 0.0f;   // sum of mask*log(lamb + 1e-8)
    float S   = 0.0f;   // sum exp(log_kernel)
    float Ms  = 0.0f;   // sum mask
    #pragma unroll
    for (int j = 0; j < CHUNK; ++j) {
        A2 = g[j] * (A2 + 1.0f);
        float lamb = alpha * A2 + mu;
        float mj = mv[j];
        acc += mj * logf(lamb + 1e-8f);
        float lk = -beta * (t1 - tv[j]) * mj + (1.0f - mj) * NEG;
        S += expf(lk);
        Ms += mj;
    }

    // ---- block reductions ----
    sP[k] = acc; sQ[k] = S; sR[k] = Ms;
    __syncthreads();
    #pragma unroll
    for (int d = BLK / 2; d > 0; d >>= 1) {
        if (k < d) {
            sP[k] += sP[k + d];
            sQ[k] += sQ[k + d];
            sR[k] += sR[k + d];
        }
        __syncthreads();
    }

    if (k == 0) {
        float loglik = sP[0];
        float comp = (t1 - t0) * mu - (alpha / beta) * (sQ[0] - sR[0]);
        out[n] = loglik - comp;
    }
}

extern "C" void kernel_launch(void* const* d_in, const int* in_sizes, int n_in,
                              void* d_out, int out_size)
{
    const float* event_times = (const float*)d_in[0];
    const float* input_mask  = (const float*)d_in[1];
    const float* t0          = (const float*)d_in[2];
    const float* t1          = (const float*)d_in[3];
    const float* mu          = (const float*)d_in[4];
    const float* alpha       = (const float*)d_in[5];
    const float* beta        = (const float*)d_in[6];
    float* out = (float*)d_out;

    const int N = in_sizes[2];  // t0 has N elements

    hawkes_kernel<<<N, BLK>>>(event_times, input_mask, t0, t1, mu, alpha, beta, out);
}

// round 2
// speedup vs baseline: 1.2558x; 1.2558x over previous
#include <cuda_runtime.h>
#include <cuda_bf16.h>

// Hawkes log-likelihood, N=16, T=2048. O(T) affine-recurrence reformulation:
//   A[i] = g[i]*(A[i-1]+1),  g[i] = exp(-beta*(t_i - t_{i-1})),  A[0]=0.
// R2: shuffle-based affine scan (3 barriers total), fast MUFU intrinsics,
// float4 vectorized loads. Latency-bound kernel; all changes target the
// dependent-chain length, not throughput.

#define TT 2048
#define BLK 256
#define CHUNK 8
#define NW (BLK / 32)   // 8 warps

__global__ __launch_bounds__(BLK)
void hawkes_kernel(const float* __restrict__ et,
                   const float* __restrict__ mask,
                   const float* __restrict__ t0p,
                   const float* __restrict__ t1p,
                   const float* __restrict__ mup,
                   const float* __restrict__ alphap,
                   const float* __restrict__ betap,
                   float* __restrict__ out)
{
    const int n    = blockIdx.x;
    const int k    = threadIdx.x;
    const int lane = k & 31;
    const int wid  = k >> 5;

    const float* t = et   + n * TT;
    const float* m = mask + n * TT;
    const int base = k * CHUNK;

    // ---- front-batched vector loads (4x LDG.128 + 1 scalar) ----
    const float4 ta = __ldg((const float4*)(t + base));
    const float4 tb = __ldg((const float4*)(t + base + 4));
    const float4 ma = __ldg((const float4*)(m + base));
    const float4 mb = __ldg((const float4*)(m + base + 4));
    const float tm1 = (base == 0) ? 0.0f : __ldg(t + base - 1);
    const float t0  = __ldg(t0p + n);
    const float t1  = __ldg(t1p + n);

    // softplus of scalar params (fast MUFU path; ~1e-7 rel err, tol is 1e-3)
    const float mu    = __logf(1.0f + __expf(__ldg(mup)));
    const float alpha = __logf(1.0f + __expf(__ldg(alphap)));
    const float beta  = __logf(1.0f + __expf(__ldg(betap)));

    float tv[CHUNK] = {ta.x, ta.y, ta.z, ta.w, tb.x, tb.y, tb.z, tb.w};
    float mv[CHUNK] = {ma.x, ma.y, ma.z, ma.w, mb.x, mb.y, mb.z, mb.w};

    // ---- local pass: per-element g (independent MUFU exps), local (P,Q) ----
    float g[CHUNK];
    float tprev = tm1;
    float A = 0.0f;
    #pragma unroll
    for (int j = 0; j < CHUNK; ++j) {
        float gj = __expf(-beta * (tv[j] - tprev));
        if (base + j == 0) gj = 0.0f;
        g[j] = gj;
        tprev = tv[j];
        A = fmaf(gj, A, gj);         // g*(A+1)
    }
    // chunk P telescopes to one exp; thread 0 contains global idx 0 -> P=0
    float p = (k == 0) ? 0.0f : __expf(-beta * (tv[CHUNK - 1] - tm1));
    float q = A;

    // ---- intra-warp inclusive affine scan (5 shfl steps, no barriers) ----
    #pragma unroll
    for (int d = 1; d < 32; d <<= 1) {
        float pe = __shfl_up_sync(0xffffffffu, p, d);
        float qe = __shfl_up_sync(0xffffffffu, q, d);
        if (lane >= d) {
            q = fmaf(p, qe, q);
            p = p * pe;
        }
    }

    // ---- cross-warp scan: warp 0 scans the 8 warp aggregates ----
    __shared__ float sWP[NW], sWQ[NW];
    __shared__ float sAcc[NW], sS[NW], sMs[NW];
    if (lane == 31) { sWP[wid] = p; sWQ[wid] = q; }
    __syncthreads();                                   // barrier 1
    if (wid == 0) {
        float wp = (lane < NW) ? sWP[lane] : 1.0f;
        float wq = (lane < NW) ? sWQ[lane] : 0.0f;
        #pragma unroll
        for (int d = 1; d < NW; d <<= 1) {
            float pe = __shfl_up_sync(0xffffffffu, wp, d);
            float qe = __shfl_up_sync(0xffffffffu, wq, d);
            if (lane >= d) {
                wq = fmaf(wp, qe, wq);
                wp = wp * pe;
            }
        }
        if (lane < NW) { sWP[lane] = wp; sWQ[lane] = wq; }
    }
    __syncthreads();                                   // barrier 2

    // exclusive prefix for this thread:
    //   intra-warp exclusive (shfl_up inclusive by 1; identity at lane 0)
    //   composed after the previous warps' aggregate Q.
    float pie = __shfl_up_sync(0xffffffffu, p, 1);
    float qie = __shfl_up_sync(0xffffffffu, q, 1);
    if (lane == 0) { pie = 1.0f; qie = 0.0f; }
    const float qw  = (wid == 0) ? 0.0f : sWQ[wid - 1];
    const float Ain = fmaf(pie, qw, qie);

    // ---- replay: log-likelihood + compensator terms ----
    const float NEG = -1e20f;
    float A2  = Ain;
    float acc = 0.0f, S = 0.0f, Ms = 0.0f;
    #pragma unroll
    for (int j = 0; j < CHUNK; ++j) {
        A2 = fmaf(g[j], A2, g[j]);                     // g*(A+1)
        float lamb = fmaf(alpha, A2, mu);
        float mj = mv[j];
        acc += mj * __logf(lamb + 1e-8f);
        float lk = -beta * (t1 - tv[j]) * mj + (1.0f - mj) * NEG;
        S  += __expf(lk);
        Ms += mj;
    }

    // ---- reduction: warp shfl, then warp 0 finishes (1 barrier) ----
    #pragma unroll
    for (int d = 16; d > 0; d >>= 1) {
        acc += __shfl_xor_sync(0xffffffffu, acc, d);
        S   += __shfl_xor_sync(0xffffffffu, S,   d);
        Ms  += __shfl_xor_sync(0xffffffffu, Ms,  d);
    }
    if (lane == 0) { sAcc[wid] = acc; sS[wid] = S; sMs[wid] = Ms; }
    __syncthreads();                                   // barrier 3
    if (wid == 0 && lane < NW) {
        float a2 = sAcc[lane], s2 = sS[lane], m2 = sMs[lane];
        #pragma unroll
        for (int d = NW / 2; d > 0; d >>= 1) {
            a2 += __shfl_xor_sync(0xffffffffu, a2, d);
            s2 += __shfl_xor_sync(0xffffffffu, s2, d);
            m2 += __shfl_xor_sync(0xffffffffu, m2, d);
        }
        if (lane == 0) {
            float comp = (t1 - t0) * mu - (alpha / beta) * (s2 - m2);
            out[n] = a2 - comp;
        }
    }
}

extern "C" void kernel_launch(void* const* d_in, const int* in_sizes, int n_in,
                              void* d_out, int out_size)
{
    const float* event_times = (const float*)d_in[0];
    const float* input_mask  = (const float*)d_in[1];
    const float* t0          = (const float*)d_in[2];
    const float* t1          = (const float*)d_in[3];
    const float* mu          = (const float*)d_in[4];
    const float* alpha       = (const float*)d_in[5];
    const float* beta        = (const float*)d_in[6];
    float* out = (float*)d_out;

    const int N = in_sizes[2];  // t0 has N elements

    hawkes_kernel<<<N, BLK>>>(event_times, input_mask, t0, t1, mu, alpha, beta, out);
}

// round 3
// speedup vs baseline: 1.3171x; 1.0488x over previous
#include <cuda_runtime.h>
#include <cuda_bf16.h>

// Hawkes log-likelihood, N=16, T=2048. O(T) affine-recurrence reformulation:
//   A[i] = g[i]*(A[i-1]+1),  g[i] = exp(-beta*(t_i - t_{i-1})),  A[0]=0.
// R3: (1) per-thread log-of-product instead of sum-of-logs (1 log vs 8),
//     (2) compensator exps telescoped through g (1 exp vs 8),
//     (3) redundant cross-warp scan in every warp -> only 2 barriers.

#define TT 2048
#define BLK 256
#define CHUNK 8
#define NW (BLK / 32)   // 8 warps

__global__ __launch_bounds__(BLK)
void hawkes_kernel(const float* __restrict__ et,
                   const float* __restrict__ mask,
                   const float* __restrict__ t0p,
                   const float* __restrict__ t1p,
                   const float* __restrict__ mup,
                   const float* __restrict__ alphap,
                   const float* __restrict__ betap,
                   float* __restrict__ out)
{
    const int n    = blockIdx.x;
    const int k    = threadIdx.x;
    const int lane = k & 31;
    const int wid  = k >> 5;

    // ---- issue all loads up front (params first: beta gates everything) ----
    const float mur = __ldg(mup);
    const float alr = __ldg(alphap);
    const float ber = __ldg(betap);

    const float* t = et   + n * TT;
    const float* m = mask + n * TT;
    const int base = k * CHUNK;

    const float4 ta = __ldg((const float4*)(t + base));
    const float4 tb = __ldg((const float4*)(t + base + 4));
    const float4 ma = __ldg((const float4*)(m + base));
    const float4 mb = __ldg((const float4*)(m + base + 4));
    const float tm1 = (base == 0) ? 0.0f : __ldg(t + base - 1);
    const float t0  = __ldg(t0p + n);
    const float t1  = __ldg(t1p + n);

    // softplus (fast MUFU path; tolerance is 1e-3, we're at ~1e-6)
    const float mu    = __logf(1.0f + __expf(mur));
    const float alpha = __logf(1.0f + __expf(alr));
    const float beta  = __logf(1.0f + __expf(ber));

    float tv[CHUNK] = {ta.x, ta.y, ta.z, ta.w, tb.x, tb.y, tb.z, tb.w};
    float mv[CHUNK] = {ma.x, ma.y, ma.z, ma.w, mb.x, mb.y, mb.z, mb.w};

    // ---- local pass: per-element g (independent MUFU exps), local (P,Q) ----
    float g[CHUNK];
    float tprev = tm1;
    float A = 0.0f;
    #pragma unroll
    for (int j = 0; j < CHUNK; ++j) {
        float gj = __expf(-beta * (tv[j] - tprev));
        if (base + j == 0) gj = 0.0f;
        g[j] = gj;
        tprev = tv[j];
        A = fmaf(gj, A, gj);                     // g*(A+1)
    }
    // chunk P telescopes to one exp; thread 0 holds global idx 0 -> P=0
    float p = (k == 0) ? 0.0f : __expf(-beta * (tv[CHUNK - 1] - tm1));
    float q = A;

    // ---- intra-warp inclusive affine scan (5 shfl steps, no barriers) ----
    #pragma unroll
    for (int d = 1; d < 32; d <<= 1) {
        float pe = __shfl_up_sync(0xffffffffu, p, d);
        float qe = __shfl_up_sync(0xffffffffu, q, d);
        if (lane >= d) {
            q = fmaf(p, qe, q);
            p = p * pe;
        }
    }

    // ---- cross-warp: every warp redundantly scans the 8 aggregates ----
    __shared__ float sWP[NW], sWQ[NW];
    __shared__ float sAcc[NW], sS[NW], sMs[NW];
    if (lane == 31) { sWP[wid] = p; sWQ[wid] = q; }
    __syncthreads();                                   // barrier 1
    {
        float wp = (lane < NW) ? sWP[lane] : 1.0f;
        float wq = (lane < NW) ? sWQ[lane] : 0.0f;
        #pragma unroll
        for (int d = 1; d < NW; d <<= 1) {
            float pe = __shfl_up_sync(0xffffffffu, wp, d);
            float qe = __shfl_up_sync(0xffffffffu, wq, d);
            if (lane >= d) {
                wq = fmaf(wp, qe, wq);
                wp = wp * pe;
            }
        }
        // Q entering this warp = inclusive scan at lane (wid-1)
        float qw = __shfl_sync(0xffffffffu, wq, (wid == 0) ? 0 : (wid - 1));
        if (wid == 0) qw = 0.0f;

        // thread-exclusive prefix inside the warp, composed after qw
        float pie = __shfl_up_sync(0xffffffffu, p, 1);
        float qie = __shfl_up_sync(0xffffffffu, q, 1);
        if (lane == 0) { pie = 1.0f; qie = 0.0f; }
        A = fmaf(pie, qw, qie);                        // Ain for this thread
    }

    // ---- replay ----
    // loglik: one log of the product of (1 + m*(lamb+1e-8-1)) over the chunk
    // compensator: exp(-beta*(t1-t_j)) telescoped backward through g
    float prodL = 1.0f;
    #pragma unroll
    for (int j = 0; j < CHUNK; ++j) {
        A = fmaf(g[j], A, g[j]);                       // g*(A+1)
        float lamb = fmaf(alpha, A, mu) + 1e-8f;
        prodL *= fmaf(mv[j], lamb - 1.0f, 1.0f);       // m? lamb : 1
    }
    float acc = __logf(prodL);

    float w = __expf(-beta * (t1 - tv[CHUNK - 1]));    // the only exp here
    float S = mv[CHUNK - 1] * w;
    float Ms = mv[CHUNK - 1];
    #pragma unroll
    for (int j = CHUNK - 2; j >= 0; --j) {
        w *= g[j + 1];                                 // -> exp(-beta*(t1-t_j))
        S  = fmaf(mv[j], w, S);
        Ms += mv[j];
    }

    // ---- reduction: warp shfl, then warp 0 finishes (1 barrier) ----
    #pragma unroll
    for (int d = 16; d > 0; d >>= 1) {
        acc += __shfl_xor_sync(0xffffffffu, acc, d);
        S   += __shfl_xor_sync(0xffffffffu, S,   d);
        Ms  += __shfl_xor_sync(0xffffffffu, Ms,  d);
    }
    if (lane == 0) { sAcc[wid] = acc; sS[wid] = S; sMs[wid] = Ms; }
    __syncthreads();                                   // barrier 2
    if (wid == 0 && lane < NW) {
        float a2 = sAcc[lane], s2 = sS[lane], m2 = sMs[lane];
        #pragma unroll
        for (int d = NW / 2; d > 0; d >>= 1) {
            a2 += __shfl_xor_sync(0xffffffffu, a2, d);
            s2 += __shfl_xor_sync(0xffffffffu, s2, d);
            m2 += __shfl_xor_sync(0xffffffffu, m2, d);
        }
        if (lane == 0) {
            float comp = (t1 - t0) * mu - (alpha / beta) * (s2 - m2);
            out[n] = a2 - comp;
        }
    }
}

extern "C" void kernel_launch(void* const* d_in, const int* in_sizes, int n_in,
                              void* d_out, int out_size)
{
    const float* event_times = (const float*)d_in[0];
    const float* input_mask  = (const float*)d_in[1];
    const float* t0          = (const float*)d_in[2];
    const float* t1          = (const float*)d_in[3];
    const float* mu          = (const float*)d_in[4];
    const float* alpha       = (const float*)d_in[5];
    const float* beta        = (const float*)d_in[6];
    float* out = (float*)d_out;

    const int N = in_sizes[2];  // t0 has N elements

    hawkes_kernel<<<N, BLK>>>(event_times, input_mask, t0, t1, mu, alpha, beta, out);
}